// round 5
// baseline (speedup 1.0000x reference)
#include <cuda_runtime.h>
#include <cstdint>

#define NPT   4096
#define BATCH 4
#define KNN   20
#define NEG   0.2f
#define BNEPS 1e-5f
#define MAXC  256

#define RB    32                  // rows per block (fused knn)
#define JT    (NPT / 128)         // 32 column tiles of 128
#define CAP   64                  // per-row candidate buffer

// ---------------- scratch (device globals; no runtime allocation) ----------
__device__ float g_feat[(size_t)BATCH * NPT * MAXC];   // layer activations
__device__ float g_Pp[(size_t)BATCH * NPT * MAXC];     // s * (W1 . x_j)
__device__ float g_Qq[(size_t)BATCH * NPT * MAXC];     // s * ((W2-W1) . x_n) + t
__device__ float g_sq[BATCH * NPT];
__device__ int   g_idx[BATCH * NPT * KNN];

// packed f32x2 helpers (FFMA2: 2x fp32 throughput on sm_103a)
__device__ __forceinline__ unsigned long long pack2(float lo, float hi) {
    unsigned long long r;
    asm("mov.b64 %0, {%1, %2};" : "=l"(r) : "r"(__float_as_uint(lo)), "r"(__float_as_uint(hi)));
    return r;
}
__device__ __forceinline__ unsigned long long dup2(float v) {
    unsigned long long r;
    asm("mov.b64 %0, {%1, %1};" : "=l"(r) : "r"(__float_as_uint(v)));
    return r;
}
__device__ __forceinline__ void ffma2(unsigned long long& d, unsigned long long a, unsigned long long b) {
    asm("fma.rn.f32x2 %0, %1, %2, %0;" : "+l"(d) : "l"(a), "l"(b));
}
__device__ __forceinline__ void unpack2(unsigned long long v, float& lo, float& hi) {
    unsigned r0, r1;
    asm("mov.b64 {%0, %1}, %2;" : "=r"(r0), "=r"(r1) : "l"(v));
    lo = __uint_as_float(r0); hi = __uint_as_float(r1);
}

// ---------------- squared norms: one warp per point -------------------------
__global__ void sqnorm_kernel(const float* __restrict__ feat, int C) {
    const float* f = feat ? feat : g_feat;
    int gw   = (blockIdx.x * blockDim.x + threadIdx.x) >> 5;
    int lane = threadIdx.x & 31;
    if (gw >= BATCH * NPT) return;
    const float* r = f + (size_t)gw * C;
    float s = 0.f;
    for (int c = lane; c < C; c += 32) { float v = r[c]; s += v * v; }
    #pragma unroll
    for (int o = 16; o; o >>= 1) s += __shfl_down_sync(0xffffffffu, s, o);
    if (!lane) g_sq[gw] = s;
}

// ---------------- warp-level exact top-20 of n (<=64) buffered candidates ---
// Returns the 20th-largest value. Reorders buf[0..19] = top-20.
__device__ __forceinline__ float warp_top20(float* bv, int* bi, int n, int lane) {
    float v0 = (lane      < n) ? bv[lane]      : -3.4e38f;
    int   x0 = (lane      < n) ? bi[lane]      : 0;
    float v1 = (lane + 32 < n) ? bv[lane + 32] : -3.4e38f;
    int   x1 = (lane + 32 < n) ? bi[lane + 32] : 0;
    __syncwarp();
    float last = -3.4e38f;
    #pragma unroll 1
    for (int r = 0; r < KNN; r++) {
        bool s1 = v1 > v0;
        float cv = s1 ? v1 : v0;
        int   ci = s1 ? x1 : x0;
        int   code = (lane << 1) | (s1 ? 1 : 0);
        #pragma unroll
        for (int o = 16; o; o >>= 1) {
            float ov = __shfl_xor_sync(0xffffffffu, cv, o);
            int   oi = __shfl_xor_sync(0xffffffffu, ci, o);
            int   oc = __shfl_xor_sync(0xffffffffu, code, o);
            if (ov > cv || (ov == cv && oc < code)) { cv = ov; ci = oi; code = oc; }
        }
        if ((code >> 1) == lane) { if (code & 1) v1 = -3.4e38f; else v0 = -3.4e38f; }
        if (lane == 0) { bv[r] = cv; bi[r] = ci; }
        last = cv;
    }
    __syncwarp();
    return last;
}

// ---------------- FUSED distance GEMM + streaming top-20 --------------------
// One block owns 32 rows; streams all 4096 columns in 128-wide tiles;
// maintains per-row top-20 via threshold + append buffer + rare compaction.
// No distance matrix is ever materialized.
__global__ __launch_bounds__(256, 3) void fused_knn(const float* __restrict__ feat, int C) {
    const float* f = feat ? feat : g_feat;
    int b  = blockIdx.y;
    int i0 = blockIdx.x * RB;
    const float* A   = f    + (size_t)b * NPT * C;
    const float* sqb = g_sq + b * NPT;

    __shared__ __align__(16) float As[128][RB + 1];     // [k][row]
    __shared__ __align__(16) float Bs[2][16][132];
    __shared__ float bufv[RB][CAP];
    __shared__ int   bufi[RB][CAP];
    __shared__ float thr_s[RB];
    __shared__ int   cnt_s[RB];
    __shared__ float sqj[128];
    __shared__ unsigned ovf;

    int tid  = threadIdx.x;
    int lane = tid & 31, wid = tid >> 5;
    int tx = tid & 15, ty = tid >> 4;
    int r0 = 2 * ty;            // local rows r0, r0+1
    int tj = tx * 8;            // 8-col octet

    if (tid < RB) { thr_s[tid] = -3.4e38f; cnt_s[tid] = 0; }
    if (tid == 0) ovf = 0u;

    // resident A panel [kmax][RB], zero-padded in k
    int kmax = (C + 15) & ~15;
    for (int idx = tid; idx < kmax * RB; idx += 256) {
        int r = idx / kmax, k = idx - r * kmax;
        As[k][r] = (k < C) ? A[(size_t)(i0 + r) * C + k] : 0.f;
    }
    __syncthreads();

    float si0 = sqb[i0 + r0], si1 = sqb[i0 + r0 + 1];
    int nk = kmax >> 4;

    #pragma unroll 1
    for (int jt = 0; jt < JT; jt++) {
        int j0 = jt * 128;

        if (tid < 128) sqj[tid] = sqb[j0 + tid];
        // load B chunk 0
        #pragma unroll
        for (int q = 0; q < 8; q++) {
            int lin = tid + q * 256;
            int col = lin >> 4, k = lin & 15;
            Bs[0][k][col] = (k < C) ? A[(size_t)(j0 + col) * C + k] : 0.f;
        }
        __syncthreads();

        unsigned long long acc[2][4];
        #pragma unroll
        for (int r = 0; r < 2; r++)
            #pragma unroll
            for (int p = 0; p < 4; p++) acc[r][p] = 0ull;

        #pragma unroll 1
        for (int kc = 0; kc < nk; kc++) {
            int cur = kc & 1;
            float rb[8];
            bool more = (kc + 1) < nk;
            if (more) {
                int k0 = (kc + 1) * 16;
                #pragma unroll
                for (int q = 0; q < 8; q++) {
                    int lin = tid + q * 256;
                    int col = lin >> 4, k = k0 + (lin & 15);
                    rb[q] = (k < C) ? A[(size_t)(j0 + col) * C + k] : 0.f;
                }
            }
            #pragma unroll
            for (int kk = 0; kk < 16; kk++) {
                float a0 = As[kc * 16 + kk][r0];
                float a1 = As[kc * 16 + kk][r0 + 1];
                float4 b0 = *(const float4*)&Bs[cur][kk][tj];
                float4 b1 = *(const float4*)&Bs[cur][kk][tj + 4];
                unsigned long long bp[4];
                bp[0] = pack2(b0.x, b0.y); bp[1] = pack2(b0.z, b0.w);
                bp[2] = pack2(b1.x, b1.y); bp[3] = pack2(b1.z, b1.w);
                unsigned long long ad0 = dup2(a0), ad1 = dup2(a1);
                #pragma unroll
                for (int p = 0; p < 4; p++) { ffma2(acc[0][p], ad0, bp[p]); ffma2(acc[1][p], ad1, bp[p]); }
            }
            if (more) {
                int nxt = cur ^ 1;
                #pragma unroll
                for (int q = 0; q < 8; q++) {
                    int lin = tid + q * 256;
                    int col = lin >> 4, k = lin & 15;
                    Bs[nxt][k][col] = rb[q];
                }
            }
            __syncthreads();
        }

        // distances for this tile: dv[2][8]
        float dv[2][8];
        float sj[8];
        #pragma unroll
        for (int c = 0; c < 8; c++) sj[c] = sqj[tj + c];
        #pragma unroll
        for (int p = 0; p < 4; p++) {
            float lo, hi;
            unpack2(acc[0][p], lo, hi);
            dv[0][2 * p]     = 2.f * lo - si0 - sj[2 * p];
            dv[0][2 * p + 1] = 2.f * hi - si0 - sj[2 * p + 1];
            unpack2(acc[1][p], lo, hi);
            dv[1][2 * p]     = 2.f * lo - si1 - sj[2 * p];
            dv[1][2 * p + 1] = 2.f * hi - si1 - sj[2 * p + 1];
        }

        // threshold-filtered append with retry-on-overflow
        unsigned todo = 0xFFFFu;
        #pragma unroll 1
        while (true) {
            #pragma unroll
            for (int v = 0; v < 16; v++) {
                if (todo & (1u << v)) {
                    int r  = v >> 3, c = v & 7;
                    int rl = r0 + r;
                    float val = dv[r][c];
                    if (val > thr_s[rl]) {
                        int pos = atomicAdd(&cnt_s[rl], 1);
                        if (pos < CAP) {
                            bufv[rl][pos] = val;
                            bufi[rl][pos] = j0 + tj + c;
                            todo &= ~(1u << v);
                        } else {
                            atomicOr(&ovf, 1u << rl);
                        }
                    } else todo &= ~(1u << v);
                }
            }
            __syncthreads();
            unsigned mask = ovf;
            if (mask == 0u) break;
            __syncthreads();                 // everyone has read mask
            if (tid == 0) ovf = 0u;
            for (int rr = wid; rr < RB; rr += 8) {
                if (mask & (1u << rr)) {
                    int n = cnt_s[rr]; if (n > CAP) n = CAP;
                    float t20 = warp_top20(bufv[rr], bufi[rr], n, lane);
                    if (lane == 0) { cnt_s[rr] = KNN; thr_s[rr] = t20; }
                }
            }
            __syncthreads();                 // thr/cnt/ovf visible; retry
        }
    }

    // final exact top-20 per row and emit indices
    for (int rr = wid; rr < RB; rr += 8) {
        int n = cnt_s[rr]; if (n > CAP) n = CAP;
        warp_top20(bufv[rr], bufi[rr], n, lane);
        if (lane < KNN)
            g_idx[((size_t)b * NPT + i0 + rr) * KNN + lane] = bufi[rr][lane];
    }
}

// ---------------- fused P/Q GEMM with folded BatchNorm -----------------------
__global__ __launch_bounds__(256) void pq_gemm(
    const float* __restrict__ feat, const float* __restrict__ W,
    const float* __restrict__ gg, const float* __restrict__ bb,
    const float* __restrict__ mm, const float* __restrict__ vv,
    int C, int O)
{
    const float* f = feat ? feat : g_feat;
    int i0 = blockIdx.y * 64;
    int o0 = blockIdx.x * 64;

    __shared__ __align__(16) float As[16][68];
    __shared__ __align__(16) float B1[16][68];
    __shared__ __align__(16) float B2[16][68];

    int tid = threadIdx.x;
    int tx = tid & 15, ty = tid >> 4;
    int lc = tid & 15, lr0 = tid >> 4;
    int twoC = 2 * C;

    float acc1[4][4], acc2[4][4];
    #pragma unroll
    for (int i = 0; i < 4; i++)
        #pragma unroll
        for (int j = 0; j < 4; j++) { acc1[i][j] = 0.f; acc2[i][j] = 0.f; }

    for (int k0 = 0; k0 < C; k0 += 16) {
        bool kin = (k0 + lc) < C;
        #pragma unroll
        for (int q = 0; q < 4; q++) {
            int r = lr0 + q * 16;
            As[lc][r] = kin ? f[(size_t)(i0 + r) * C + k0 + lc] : 0.f;
            B1[lc][r] = kin ? W[(size_t)(o0 + r) * twoC + k0 + lc] : 0.f;
            B2[lc][r] = kin ? W[(size_t)(o0 + r) * twoC + C + k0 + lc] : 0.f;
        }
        __syncthreads();
        #pragma unroll
        for (int kk = 0; kk < 16; kk++) {
            float4 a4  = *(const float4*)&As[kk][ty * 4];
            float4 b14 = *(const float4*)&B1[kk][tx * 4];
            float4 b24 = *(const float4*)&B2[kk][tx * 4];
            float av[4]  = {a4.x, a4.y, a4.z, a4.w};
            float b1v[4] = {b14.x, b14.y, b14.z, b14.w};
            float b2v[4] = {b24.x, b24.y, b24.z, b24.w};
            #pragma unroll
            for (int i = 0; i < 4; i++)
                #pragma unroll
                for (int j = 0; j < 4; j++) {
                    acc1[i][j] += av[i] * b1v[j];
                    acc2[i][j] += av[i] * b2v[j];
                }
        }
        __syncthreads();
    }

    #pragma unroll
    for (int j = 0; j < 4; j++) {
        int o = o0 + tx * 4 + j;
        float s = gg[o] * rsqrtf(vv[o] + BNEPS);
        float t = bb[o] - s * mm[o];
        #pragma unroll
        for (int i = 0; i < 4; i++) {
            int gi = i0 + ty * 4 + i;
            g_Pp[(size_t)gi * O + o] = s * acc1[i][j];
            g_Qq[(size_t)gi * O + o] = s * (acc2[i][j] - acc1[i][j]) + t;
        }
    }
}

// ---------------- gather neighbors + max + leaky relu ------------------------
__global__ __launch_bounds__(128) void gmax_kernel(int O, float* __restrict__ outp) {
    float* out = outp ? outp : g_feat;
    int bn = blockIdx.x;
    int b  = bn / NPT;
    __shared__ int sidx[KNN];
    if (threadIdx.x < KNN) sidx[threadIdx.x] = g_idx[bn * KNN + threadIdx.x];
    __syncthreads();
    size_t base = (size_t)b * NPT;
    for (int o = threadIdx.x; o < O; o += blockDim.x) {
        float q = g_Qq[(size_t)bn * O + o];
        float m = -3.4e38f;
        #pragma unroll
        for (int k = 0; k < KNN; k++) {
            float v = g_Pp[(base + sidx[k]) * O + o] + q;
            m = fmaxf(m, v);
        }
        out[(size_t)bn * O + o] = (m >= 0.f) ? m : NEG * m;
    }
}

// ---------------- host orchestration ----------------------------------------
extern "C" void kernel_launch(void* const* d_in, const int* in_sizes, int n_in,
                              void* d_out, int out_size)
{
    (void)in_sizes; (void)n_in; (void)out_size;
    const float* x = (const float*)d_in[0];
    static const int dims[5] = {3, 64, 64, 128, 256};

    const float* fin = x;
    for (int l = 0; l < 4; l++) {
        int C = dims[l], O = dims[l + 1];
        const float* Wl = (const float*)d_in[1 + l * 5];
        const float* gl = (const float*)d_in[2 + l * 5];
        const float* bl = (const float*)d_in[3 + l * 5];
        const float* ml = (const float*)d_in[4 + l * 5];
        const float* vl = (const float*)d_in[5 + l * 5];

        sqnorm_kernel<<<(BATCH * NPT) / 8, 256>>>(fin, C);
        fused_knn<<<dim3(NPT / RB, BATCH), 256>>>(fin, C);
        pq_gemm<<<dim3(O / 64, (BATCH * NPT) / 64), 256>>>(fin, Wl, gl, bl, ml, vl, C, O);
        gmax_kernel<<<BATCH * NPT, 128>>>(O, (l == 3) ? (float*)d_out : nullptr);

        fin = nullptr;
    }
}

// round 6
// speedup vs baseline: 2.2323x; 2.2323x over previous
#include <cuda_runtime.h>
#include <cstdint>

#define NPT   4096
#define BATCH 4
#define KNN   20
#define NEG   0.2f
#define BNEPS 1e-5f
#define MAXC  256

#define BT    128                 // dist gemm tile (BM=BN=128)
#define NTIL  (NPT / BT)          // 32 tiles per dim
#define NTRI  (NTIL * (NTIL + 1) / 2)   // 528 upper-tri block pairs
#define BK    16                  // dist gemm k-tile

// ---------------- scratch (device globals; no runtime allocation) ----------
__device__ float g_D[(size_t)BATCH * NPT * NPT];       // 256 MiB distance matrix
__device__ float g_feat[(size_t)BATCH * NPT * MAXC];   // layer activations
__device__ float g_Pp[(size_t)BATCH * NPT * MAXC];     // s * (W1 . x_j)
__device__ float g_Qq[(size_t)BATCH * NPT * MAXC];     // s * ((W2-W1) . x_n) + t
__device__ float g_sq[BATCH * NPT];
__device__ int   g_idx[BATCH * NPT * KNN];

// packed f32x2 helpers (FFMA2: 2x fp32 throughput on sm_103a)
__device__ __forceinline__ unsigned long long pack2(float lo, float hi) {
    unsigned long long r;
    asm("mov.b64 %0, {%1, %2};" : "=l"(r) : "r"(__float_as_uint(lo)), "r"(__float_as_uint(hi)));
    return r;
}
__device__ __forceinline__ unsigned long long dup2(float v) {
    unsigned long long r;
    asm("mov.b64 %0, {%1, %1};" : "=l"(r) : "r"(__float_as_uint(v)));
    return r;
}
__device__ __forceinline__ void ffma2(unsigned long long& d, unsigned long long a, unsigned long long b) {
    asm("fma.rn.f32x2 %0, %1, %2, %0;" : "+l"(d) : "l"(a), "l"(b));
}
__device__ __forceinline__ void unpack2(unsigned long long v, float& lo, float& hi) {
    unsigned r0, r1;
    asm("mov.b64 {%0, %1}, %2;" : "=r"(r0), "=r"(r1) : "l"(v));
    lo = __uint_as_float(r0); hi = __uint_as_float(r1);
}

// ---------------- squared norms: one warp per point -------------------------
__global__ void sqnorm_kernel(const float* __restrict__ feat, int C) {
    const float* f = feat ? feat : g_feat;
    int gw   = (blockIdx.x * blockDim.x + threadIdx.x) >> 5;
    int lane = threadIdx.x & 31;
    if (gw >= BATCH * NPT) return;
    const float* r = f + (size_t)gw * C;
    float s = 0.f;
    for (int c = lane; c < C; c += 32) { float v = r[c]; s += v * v; }
    #pragma unroll
    for (int o = 16; o; o >>= 1) s += __shfl_down_sync(0xffffffffu, s, o);
    if (!lane) g_sq[gw] = s;
}

// ---------------- distance GEMM (symmetric, 128x128xBK16, f32x2) ------------
// NO min-blocks clause: let ptxas use ~170 regs so the 64-bit accumulator
// pairs and staging never spill. Occupancy 1 block/SM = 2 warps/SMSP, which
// saturates FFMA2 (rt_SMSP=2).
__global__ __launch_bounds__(256) void dist_gemm(const float* __restrict__ feat, int C) {
    const float* f = feat ? feat : g_feat;
    int b = blockIdx.z;
    const float* A   = f    + (size_t)b * NPT * C;
    float*       Db  = g_D  + (size_t)b * NPT * NPT;
    const float* sqb = g_sq + b * NPT;

    int p = blockIdx.x;
    int bi = 0;
    #pragma unroll 1
    while (p >= NTIL - bi) { p -= NTIL - bi; bi++; }
    int bj = bi + p;
    int i0 = bi * BT, j0 = bj * BT;

    __shared__ __align__(16) float As[2][BK][132];
    __shared__ __align__(16) float Bs[2][BK][132];

    int tid = threadIdx.x;
    int tx = tid & 15, ty = tid >> 4;
    int ti = ty * 8, tj = tx * 8;

    unsigned long long acc[8][4];
    #pragma unroll
    for (int i = 0; i < 8; i++)
        #pragma unroll
        for (int j = 0; j < 4; j++) acc[i][j] = 0ull;

    int nk = (C + BK - 1) / BK;

    // prologue: stage k-tile 0 (each thread: 8 elements per matrix)
    #pragma unroll
    for (int q = 0; q < 8; q++) {
        int lin = tid + q * 256;
        int k = lin & (BK - 1), i = lin >> 4;
        As[0][k][i] = (k < C) ? A[(size_t)(i0 + i) * C + k] : 0.f;
        Bs[0][k][i] = (k < C) ? A[(size_t)(j0 + i) * C + k] : 0.f;
    }
    __syncthreads();

    #pragma unroll 1
    for (int kt = 0; kt < nk; kt++) {
        int cur = kt & 1;
        float ra[8], rb[8];
        bool more = (kt + 1) < nk;
        if (more) {
            int k0 = (kt + 1) * BK;
            #pragma unroll
            for (int q = 0; q < 8; q++) {
                int lin = tid + q * 256;
                int k = k0 + (lin & (BK - 1)), i = lin >> 4;
                ra[q] = (k < C) ? A[(size_t)(i0 + i) * C + k] : 0.f;
                rb[q] = (k < C) ? A[(size_t)(j0 + i) * C + k] : 0.f;
            }
        }

        #pragma unroll
        for (int kk = 0; kk < BK; kk++) {
            float4 a0 = *(const float4*)&As[cur][kk][ti];
            float4 a1 = *(const float4*)&As[cur][kk][ti + 4];
            float4 b0 = *(const float4*)&Bs[cur][kk][tj];
            float4 b1 = *(const float4*)&Bs[cur][kk][tj + 4];
            unsigned long long bp[4];
            bp[0] = pack2(b0.x, b0.y); bp[1] = pack2(b0.z, b0.w);
            bp[2] = pack2(b1.x, b1.y); bp[3] = pack2(b1.z, b1.w);
            float av[8] = {a0.x, a0.y, a0.z, a0.w, a1.x, a1.y, a1.z, a1.w};
            #pragma unroll
            for (int i = 0; i < 8; i++) {
                unsigned long long ad = dup2(av[i]);
                ffma2(acc[i][0], ad, bp[0]);
                ffma2(acc[i][1], ad, bp[1]);
                ffma2(acc[i][2], ad, bp[2]);
                ffma2(acc[i][3], ad, bp[3]);
            }
        }

        if (more) {
            int nxt = cur ^ 1;
            #pragma unroll
            for (int q = 0; q < 8; q++) {
                int lin = tid + q * 256;
                int k = lin & (BK - 1), i = lin >> 4;
                As[nxt][k][i] = ra[q];
                Bs[nxt][k][i] = rb[q];
            }
        }
        __syncthreads();
    }

    int gi0 = i0 + ti, gj0 = j0 + tj;
    float si[8], sj[8], vals[8][8];
    #pragma unroll
    for (int i = 0; i < 8; i++) si[i] = sqb[gi0 + i];
    #pragma unroll
    for (int j = 0; j < 8; j++) sj[j] = sqb[gj0 + j];
    #pragma unroll
    for (int i = 0; i < 8; i++)
        #pragma unroll
        for (int jp = 0; jp < 4; jp++) {
            float lo, hi;
            unpack2(acc[i][jp], lo, hi);
            vals[i][2 * jp]     = 2.f * lo - si[i] - sj[2 * jp];
            vals[i][2 * jp + 1] = 2.f * hi - si[i] - sj[2 * jp + 1];
        }

    #pragma unroll
    for (int i = 0; i < 8; i++) {
        float4 o0 = {vals[i][0], vals[i][1], vals[i][2], vals[i][3]};
        float4 o1 = {vals[i][4], vals[i][5], vals[i][6], vals[i][7]};
        *(float4*)&Db[(size_t)(gi0 + i) * NPT + gj0]     = o0;
        *(float4*)&Db[(size_t)(gi0 + i) * NPT + gj0 + 4] = o1;
    }
    if (bi != bj) {
        #pragma unroll
        for (int j = 0; j < 8; j++) {
            float4 o0 = {vals[0][j], vals[1][j], vals[2][j], vals[3][j]};
            float4 o1 = {vals[4][j], vals[5][j], vals[6][j], vals[7][j]};
            *(float4*)&Db[(size_t)(gj0 + j) * NPT + gi0]     = o0;
            *(float4*)&Db[(size_t)(gj0 + j) * NPT + gi0 + 4] = o1;
        }
    }
}

// ---------------- top-20 per row (round-2 block version, unchanged) ---------
__global__ __launch_bounds__(256) void topk_kernel() {
    int row = blockIdx.x;
    const float* r = g_D + (size_t)row * NPT;
    __shared__ float sv[NPT];
    __shared__ float wv[8];
    __shared__ int   wi[8];
    __shared__ int   sbest;
    int tid = threadIdx.x;

    for (int j = tid; j < NPT; j += 256) sv[j] = r[j];
    __syncthreads();

    float lv = -3.4e38f; int li = NPT;
    for (int j = tid; j < NPT; j += 256) {
        float v = sv[j];
        if (v > lv) { lv = v; li = j; }
    }

    int lane = tid & 31, w = tid >> 5;
    for (int kk = 0; kk < KNN; kk++) {
        float v = lv; int i = li;
        #pragma unroll
        for (int o = 16; o; o >>= 1) {
            float ov = __shfl_down_sync(0xffffffffu, v, o);
            int   oi = __shfl_down_sync(0xffffffffu, i, o);
            if (ov > v || (ov == v && oi < i)) { v = ov; i = oi; }
        }
        if (!lane) { wv[w] = v; wi[w] = i; }
        __syncthreads();
        if (!tid) {
            float bv = wv[0]; int bi = wi[0];
            #pragma unroll
            for (int x = 1; x < 8; x++)
                if (wv[x] > bv || (wv[x] == bv && wi[x] < bi)) { bv = wv[x]; bi = wi[x]; }
            sbest = bi;
            g_idx[row * KNN + kk] = bi;
        }
        __syncthreads();
        int bi = sbest;
        if ((bi & 255) == tid) {
            sv[bi] = -3.4e38f;
            lv = -3.4e38f; li = NPT;
            for (int j = tid; j < NPT; j += 256) {
                float v2 = sv[j];
                if (v2 > lv) { lv = v2; li = j; }
            }
        }
        __syncthreads();
    }
}

// ---------------- fused P/Q GEMM with folded BatchNorm -----------------------
__global__ __launch_bounds__(256) void pq_gemm(
    const float* __restrict__ feat, const float* __restrict__ W,
    const float* __restrict__ gg, const float* __restrict__ bb,
    const float* __restrict__ mm, const float* __restrict__ vv,
    int C, int O)
{
    const float* f = feat ? feat : g_feat;
    int i0 = blockIdx.y * 64;
    int o0 = blockIdx.x * 64;

    __shared__ __align__(16) float As[16][68];
    __shared__ __align__(16) float B1[16][68];
    __shared__ __align__(16) float B2[16][68];

    int tid = threadIdx.x;
    int tx = tid & 15, ty = tid >> 4;
    int lc = tid & 15, lr0 = tid >> 4;
    int twoC = 2 * C;

    float acc1[4][4], acc2[4][4];
    #pragma unroll
    for (int i = 0; i < 4; i++)
        #pragma unroll
        for (int j = 0; j < 4; j++) { acc1[i][j] = 0.f; acc2[i][j] = 0.f; }

    for (int k0 = 0; k0 < C; k0 += 16) {
        bool kin = (k0 + lc) < C;
        #pragma unroll
        for (int q = 0; q < 4; q++) {
            int r = lr0 + q * 16;
            As[lc][r] = kin ? f[(size_t)(i0 + r) * C + k0 + lc] : 0.f;
            B1[lc][r] = kin ? W[(size_t)(o0 + r) * twoC + k0 + lc] : 0.f;
            B2[lc][r] = kin ? W[(size_t)(o0 + r) * twoC + C + k0 + lc] : 0.f;
        }
        __syncthreads();
        #pragma unroll
        for (int kk = 0; kk < 16; kk++) {
            float4 a4  = *(const float4*)&As[kk][ty * 4];
            float4 b14 = *(const float4*)&B1[kk][tx * 4];
            float4 b24 = *(const float4*)&B2[kk][tx * 4];
            float av[4]  = {a4.x, a4.y, a4.z, a4.w};
            float b1v[4] = {b14.x, b14.y, b14.z, b14.w};
            float b2v[4] = {b24.x, b24.y, b24.z, b24.w};
            #pragma unroll
            for (int i = 0; i < 4; i++)
                #pragma unroll
                for (int j = 0; j < 4; j++) {
                    acc1[i][j] += av[i] * b1v[j];
                    acc2[i][j] += av[i] * b2v[j];
                }
        }
        __syncthreads();
    }

    #pragma unroll
    for (int j = 0; j < 4; j++) {
        int o = o0 + tx * 4 + j;
        float s = gg[o] * rsqrtf(vv[o] + BNEPS);
        float t = bb[o] - s * mm[o];
        #pragma unroll
        for (int i = 0; i < 4; i++) {
            int gi = i0 + ty * 4 + i;
            g_Pp[(size_t)gi * O + o] = s * acc1[i][j];
            g_Qq[(size_t)gi * O + o] = s * (acc2[i][j] - acc1[i][j]) + t;
        }
    }
}

// ---------------- gather neighbors + max + leaky relu ------------------------
__global__ __launch_bounds__(128) void gmax_kernel(int O, float* __restrict__ outp) {
    float* out = outp ? outp : g_feat;
    int bn = blockIdx.x;
    int b  = bn / NPT;
    __shared__ int sidx[KNN];
    if (threadIdx.x < KNN) sidx[threadIdx.x] = g_idx[bn * KNN + threadIdx.x];
    __syncthreads();
    size_t base = (size_t)b * NPT;
    for (int o = threadIdx.x; o < O; o += blockDim.x) {
        float q = g_Qq[(size_t)bn * O + o];
        float m = -3.4e38f;
        #pragma unroll
        for (int k = 0; k < KNN; k++) {
            float v = g_Pp[(base + sidx[k]) * O + o] + q;
            m = fmaxf(m, v);
        }
        out[(size_t)bn * O + o] = (m >= 0.f) ? m : NEG * m;
    }
}

// ---------------- host orchestration ----------------------------------------
extern "C" void kernel_launch(void* const* d_in, const int* in_sizes, int n_in,
                              void* d_out, int out_size)
{
    (void)in_sizes; (void)n_in; (void)out_size;
    const float* x = (const float*)d_in[0];
    static const int dims[5] = {3, 64, 64, 128, 256};

    const float* fin = x;
    for (int l = 0; l < 4; l++) {
        int C = dims[l], O = dims[l + 1];
        const float* Wl = (const float*)d_in[1 + l * 5];
        const float* gl = (const float*)d_in[2 + l * 5];
        const float* bl = (const float*)d_in[3 + l * 5];
        const float* ml = (const float*)d_in[4 + l * 5];
        const float* vl = (const float*)d_in[5 + l * 5];

        sqnorm_kernel<<<(BATCH * NPT) / 8, 256>>>(fin, C);
        dist_gemm<<<dim3(NTRI, 1, BATCH), 256>>>(fin, C);
        topk_kernel<<<BATCH * NPT, 256>>>();
        pq_gemm<<<dim3(O / 64, (BATCH * NPT) / 64), 256>>>(fin, Wl, gl, bl, ml, vl, C, O);
        gmax_kernel<<<BATCH * NPT, 128>>>(O, (l == 3) ? (float*)d_out : nullptr);

        fin = nullptr;
    }
}